// round 16
// baseline (speedup 1.0000x reference)
#include <cuda_runtime.h>
#include <cuda_fp16.h>
#include <math.h>
#include <stdint.h>

// Problem constants
#define B_    256
#define N_    512
#define HID_  512
#define IN_   57
#define OUT_  57

#define MAXL      513
#define GRID_MAIN 296            // 2 CTAs/SM x 148 SMs, co-resident
#define THR_MAIN  256
#define MT        64             // nodes (rows) per item
#define NQ        128            // cols per item (quarter of N)

// ---------------- device globals ----------------
__device__ __half         g_H[(size_t)B_ * (N_ + 1) * HID_];   // fp16 h; row N_ (b=0) = zero sentinel
__device__ __half         g_Wb[HID_ * HID_];      // fragment-packed Wh^T (fp16)
__device__ unsigned short g_lvl[B_ * N_];
__device__ int            g_cntb[MAXL * B_];
__device__ int            g_base[MAXL * B_];
__device__ int            g_off[MAXL + 1];
__device__ int            g_nodes[B_ * N_];
__device__ int            g_nlv;
__device__ unsigned       g_barcnt;
__device__ unsigned       g_epoch;

// ---------------- SMEM layout ----------------
// A plane (fp16): [2 buf][64 rows][136 fp16] row stride 272 B
#define A_STRIDE 272
#define A_BUFSZ  (MT * A_STRIDE)         // 17408
#define SM_A     0                       // 2 * 17408 = 34816
#define SM_B     34816                   // 2 buf x 32768 = 65536
#define B_BUFSZ  32768
#define SM_BIH   100352                  // 512 f32 = 2048
#define SM_META  102400                  // il/ir/iv/io [64] each = 1024
#define SMEM_MAIN 103424                 // x2 CTAs = 206848 < 227KB/SM

// ---------------- PTX helpers (baseline ISA only) ----------------
__device__ __forceinline__ void mma16816(float* d, const uint32_t* a,
                                         uint32_t b0, uint32_t b1) {
    asm volatile(
        "mma.sync.aligned.m16n8k16.row.col.f32.f16.f16.f32 "
        "{%0,%1,%2,%3}, {%4,%5,%6,%7}, {%8,%9}, {%0,%1,%2,%3};\n"
        : "+f"(d[0]), "+f"(d[1]), "+f"(d[2]), "+f"(d[3])
        : "r"(a[0]), "r"(a[1]), "r"(a[2]), "r"(a[3]), "r"(b0), "r"(b1));
}
__device__ __forceinline__ void ldsm4(uint32_t* r, uint32_t a) {
    asm volatile("ldmatrix.sync.aligned.m8n8.x4.shared.b16 {%0,%1,%2,%3}, [%4];\n"
        : "=r"(r[0]), "=r"(r[1]), "=r"(r[2]), "=r"(r[3]) : "r"(a));
}
__device__ __forceinline__ void lds128(uint32_t* r, uint32_t a) {
    asm volatile("ld.shared.v4.b32 {%0,%1,%2,%3}, [%4];\n"
        : "=r"(r[0]), "=r"(r[1]), "=r"(r[2]), "=r"(r[3]) : "r"(a));
}
__device__ __forceinline__ void cp16(uint32_t dst, const void* src) {
    asm volatile("cp.async.cg.shared.global [%0], [%1], 16;" :: "r"(dst), "l"(src));
}
__device__ __forceinline__ void cp_commit() { asm volatile("cp.async.commit_group;" ::: "memory"); }
__device__ __forceinline__ void cp_wait1()  { asm volatile("cp.async.wait_group 1;" ::: "memory"); }
__device__ __forceinline__ void cp_wait0()  { asm volatile("cp.async.wait_group 0;" ::: "memory"); }
__device__ __forceinline__ uint32_t smem_u32(const void* p) {
    return (uint32_t)__cvta_generic_to_shared(p);
}

// FFMA-only tanh: tanh(x) = 1 - 2/(e^{2x}+1); exp2 via round-trick + deg-7
// Taylor; reciprocal via bit-trick seed + 3 Newton. No MUFU, no CVT.
__device__ __forceinline__ float ftanh(float x) {
    float t = fminf(fmaxf(x, -15.0f), 15.0f);
    float z = t * 2.8853900817779268f;           // 2*log2(e)*x
    float zk = z + 12582912.0f;                   // round-to-nearest-even
    float k  = zk - 12582912.0f;
    float f  = z - k;                             // f in [-0.5, 0.5]
    float p = 1.5252733814e-5f;
    p = fmaf(p, f, 1.5403530394e-4f);
    p = fmaf(p, f, 1.3333558146e-3f);
    p = fmaf(p, f, 9.6181291076e-3f);
    p = fmaf(p, f, 5.5504108664e-2f);
    p = fmaf(p, f, 2.4022650696e-1f);
    p = fmaf(p, f, 6.9314718056e-1f);
    p = fmaf(p, f, 1.0f);
    const int ib = __float_as_int(zk);
    const float sc = __int_as_float((ib + (127 - 0x4B400000)) << 23);   // 2^k
    const float E = p * sc;                       // e^{2x}
    const float d = E + 1.0f;
    float r = __int_as_float(0x7EF311C3 - __float_as_int(d));
    r = r * fmaf(-d, r, 2.0f);
    r = r * fmaf(-d, r, 2.0f);
    r = r * fmaf(-d, r, 2.0f);
    return fmaf(-2.0f, r, 1.0f);
}

// ============================================================================
// Prep kernels
// ============================================================================
extern "C" __global__ void __launch_bounds__(128)
k_levels(const int* __restrict__ L, const int* __restrict__ R)
{
    __shared__ int sli[N_], sri[N_], shist[MAXL];
    __shared__ unsigned short slv[N_];
    const int b = blockIdx.x, tid = threadIdx.x;
    for (int i = tid; i < N_; i += 128) { sli[i] = L[b * N_ + i]; sri[i] = R[b * N_ + i]; }
    for (int i = tid; i < MAXL; i += 128) shist[i] = 0;
    __syncthreads();
    if (tid == 0) {
        for (int i = 0; i < N_; ++i) {
            const int l = sli[i], r = sri[i];
            const int a = (l < 0) ? 0 : (int)slv[l];
            const int c = (r < 0) ? 0 : (int)slv[r];
            const int lv = 1 + (a > c ? a : c);
            slv[i] = (unsigned short)lv;
            shist[lv]++;
        }
    }
    __syncthreads();
    for (int i = tid; i < N_; i += 128) g_lvl[b * N_ + i] = slv[i];
    for (int l = tid; l < MAXL; l += 128) g_cntb[l * B_ + b] = shist[l];
}

extern "C" __global__ void __launch_bounds__(256)
k_prefix()
{
    __shared__ int tot[MAXL];
    __shared__ int offs[MAXL + 1];
    const int tid = threadIdx.x;
    for (int l = tid; l < MAXL; l += 256) {
        int run = 0; const int base = l * B_;
        #pragma unroll 4
        for (int b = 0; b < B_; ++b) { const int c = g_cntb[base + b]; g_base[base + b] = run; run += c; }
        tot[l] = run;
    }
    __syncthreads();
    if (tid == 0) {
        int run = 0, mx = 1;
        for (int l = 0; l < MAXL; ++l) { offs[l] = run; run += tot[l]; if (tot[l] > 0) mx = l; }
        offs[MAXL] = run;
        g_nlv = mx;
    }
    __syncthreads();
    for (int idx = tid; idx < MAXL * B_; idx += 256) g_base[idx] += offs[idx >> 8];
    for (int l = tid; l <= MAXL; l += 256) g_off[l] = offs[l];
}

// counting-sort scatter + Wh transpose/pack (merged)
extern "C" __global__ void __launch_bounds__(128)
k_scatter(const float* __restrict__ W_ih)
{
    __shared__ unsigned short slv[N_];
    __shared__ int cur[MAXL];
    __shared__ int pos[N_];
    const int b = blockIdx.x, tid = threadIdx.x;
    for (int i = tid; i < N_; i += 128) slv[i] = g_lvl[b * N_ + i];
    for (int l = tid; l < MAXL; l += 128) cur[l] = g_base[l * B_ + b];
    __syncthreads();
    if (tid == 0)
        for (int i = 0; i < N_; ++i) { const int l = slv[i]; pos[i] = cur[l]++; }
    __syncthreads();
    for (int i = tid; i < N_; i += 128) g_nodes[pos[i]] = (b << 9) | i;

    // ---- Wh transpose + fp16 pack, fragment layout for mma.B ----
    // u32 index = ((n_tile*16 + kpair)*32 + lane)*4 + ko*2 + word
    for (int t = tid; t < 2 * HID_; t += 128) {
        const int n = 2 * b + (t >> 9);          // 2 n-rows per block
        const int k = t & (HID_ - 1);
        const float w = W_ih[(size_t)(IN_ + k) * HID_ + n];
        const __half h = __float2half_rn(w);
        const int n_tile = n >> 3, kpair = k >> 5, ko = (k >> 4) & 1;
        const int lane = ((n & 7) << 2) | ((k >> 1) & 3);
        const int word = (k >> 3) & 1, elem = k & 1;
        const size_t u32i = ((size_t)(n_tile * 16 + kpair) * 32 + lane) * 4 + ko * 2 + word;
        g_Wb[u32i * 2 + elem] = h;
    }
}

// ============================================================================
// Grid-wide software barrier (pure acquire-spin; CTAs co-resident)
// ============================================================================
__device__ __forceinline__ void grid_barrier(unsigned tgt, unsigned nct)
{
    __syncthreads();
    if (threadIdx.x == 0) {
        __threadfence();
        const unsigned a = atomicAdd(&g_barcnt, 1u);
        if (a == nct - 1u) {
            g_barcnt = 0u;
            __threadfence();
            atomicExch(&g_epoch, tgt);
        } else {
            unsigned e;
            do {
                asm volatile("ld.acquire.gpu.u32 %0, [%1];"
                             : "=r"(e) : "l"((unsigned*)&g_epoch) : "memory");
            } while (e < tgt);
        }
    }
    __syncthreads();
}

// ============================================================================
// Main persistent kernel: level-parallel single-pass fp16 HMMA GEMM + tanh.
// Item: 64 nodes x 128 cols. Warp tile: 32 rows x 32 cols (2x4 warp grid).
// A = h_l + h_r (fp16 add), double-buffered SMEM, K chunks of 128.
// B = W chunk (32 KB) staged via cp.async, double-buffered, consumed by LDS.
// ============================================================================
extern "C" __global__ void __launch_bounds__(THR_MAIN, 2)
rnn_main(const int* __restrict__ L, const int* __restrict__ R,
         const int* __restrict__ V, const float* __restrict__ W_ih,
         const float* __restrict__ b_ih)
{
    extern __shared__ char sm[];
    const uint32_t smem_base = smem_u32(sm);
    float* bih = (float*)(sm + SM_BIH);
    int*   il  = (int*)(sm + SM_META);
    int*   ir  = il + MT;
    int*   iv  = ir + MT;
    int*   io  = iv + MT;

    const int tid  = threadIdx.x;
    const int wid  = tid >> 5, lane = tid & 31;

    for (int i = tid; i < HID_; i += THR_MAIN) bih[i] = b_ih[i];

    // warp tiling: 2 row groups x 4 col groups (32 cols each)
    const int wm  = (wid & 1) * 32;          // warp row base
    const int wgn = wid >> 1;                // col group (0..3)
    const uint32_t a_lane = (uint32_t)((lane & 15) * A_STRIDE + (lane >> 4) * 16);
    const uint32_t aoffm0 = (uint32_t)(wm * A_STRIDE);
    const uint32_t aoffm1 = (uint32_t)((wm + 16) * A_STRIDE);
    // B SMEM lane base for this warp: slot ((wgn*4+nt)*128 + kp*32 + lane)*16
    const uint32_t b_lane = (uint32_t)(wgn * 8192 + lane * 16);

    const int nlv = g_nlv;
    const unsigned nct = gridDim.x;

    // gather mapping: row = tid>>2, k-quarter = tid&3 (32 halves = 4 uint4)
    const int grow = tid >> 2, gks = tid & 3;
    // B copy mapping: 8 slots per thread, slot s = tid + j*256
    const uint32_t bslot_lo = (uint32_t)(tid & 127);      // kp*32 + lane part
    const int      bslot_hi = tid >> 7;                   // n-tile pair base

    #define GATHER(c, bf)                                                        \
    {                                                                            \
        const uint4* pl = (const uint4*)(g_H + (size_t)il[grow] * HID_)          \
                          + ((c) * 16 + gks * 4);                                \
        const uint4* pr = (const uint4*)(g_H + (size_t)ir[grow] * HID_)          \
                          + ((c) * 16 + gks * 4);                                \
        uint4 la[4], ra[4];                                                      \
        _Pragma("unroll")                                                        \
        for (int q = 0; q < 4; ++q) { la[q] = __ldcg(pl + q); ra[q] = __ldcg(pr + q); } \
        char* dh = sm + SM_A + (bf) * A_BUFSZ + grow * A_STRIDE + gks * 64;      \
        _Pragma("unroll")                                                        \
        for (int q = 0; q < 4; ++q) {                                            \
            const __half2* a2 = (const __half2*)&la[q];                          \
            const __half2* b2 = (const __half2*)&ra[q];                          \
            __half2 s0 = __hadd2(a2[0], b2[0]);                                  \
            __half2 s1 = __hadd2(a2[1], b2[1]);                                  \
            __half2 s2 = __hadd2(a2[2], b2[2]);                                  \
            __half2 s3 = __hadd2(a2[3], b2[3]);                                  \
            ((uint4*)dh)[q] = make_uint4(*(uint32_t*)&s0, *(uint32_t*)&s1,       \
                                         *(uint32_t*)&s2, *(uint32_t*)&s3);      \
        }                                                                        \
    }

    // Stage B chunk c into buffer bf: 2048 slots of 16B, 8 per thread.
    #define STAGE_B(c, bf)                                                       \
    {                                                                            \
        const uint4* bsrc = (const uint4*)g_Wb + (size_t)hp * 8192 + (c) * 128;  \
        const uint32_t bdst = smem_base + SM_B + (uint32_t)((bf) * B_BUFSZ);     \
        _Pragma("unroll")                                                        \
        for (int j = 0; j < 8; ++j) {                                            \
            const int sh = bslot_hi + j * 2;            /* s >> 7 */             \
            cp16(bdst + (uint32_t)((sh << 11) | (bslot_lo << 4)),                \
                 bsrc + (size_t)sh * 512 + bslot_lo);                            \
        }                                                                        \
        cp_commit();                                                             \
    }

    for (int lvl = 1; lvl <= nlv; ++lvl) {
        const int s = g_off[lvl], e = g_off[lvl + 1];
        const int items = ((e - s + MT - 1) >> 6) * 4;
        for (int w = blockIdx.x; w < items; w += (int)nct) {
            const int rt = w >> 2, hp = w & 3;            // row tile / col quarter
            const int t0 = s + rt * MT;

            // ---- node metadata ----
            if (tid < MT) {
                const int gi = t0 + tid;
                if (gi < e) {
                    const int nd = g_nodes[gi];
                    const int b = nd >> 9, i = nd & (N_ - 1);
                    int l = L[b * N_ + i]; if (l < 0) l = N_;
                    int r = R[b * N_ + i]; if (r < 0) r = N_;
                    il[tid] = b * (N_ + 1) + l;
                    ir[tid] = b * (N_ + 1) + r;
                    iv[tid] = V[b * N_ + i];
                    io[tid] = b * (N_ + 1) + i;
                } else {
                    il[tid] = N_;     // zero sentinel row (b=0)
                    ir[tid] = N_;
                    iv[tid] = -1;
                }
            }
            __syncthreads();

            float acc[2][4][4];
            #pragma unroll
            for (int mt = 0; mt < 2; ++mt)
                #pragma unroll
                for (int nt = 0; nt < 4; ++nt)
                    #pragma unroll
                    for (int q = 0; q < 4; ++q) acc[mt][nt][q] = 0.0f;

            STAGE_B(0, 0)
            GATHER(0, 0)

            #pragma unroll
            for (int c = 0; c < 4; ++c) {
                if (c < 3) {
                    STAGE_B(c + 1, (c + 1) & 1)
                    GATHER(c + 1, (c + 1) & 1)
                    cp_wait1();           // B chunk c complete (newest pending)
                } else {
                    cp_wait0();
                }
                __syncthreads();          // B chunk c + A chunk c visible

                const uint32_t abA = smem_base + SM_A + (uint32_t)((c & 1) * A_BUFSZ) + a_lane;
                const uint32_t bbB = smem_base + SM_B + (uint32_t)((c & 1) * B_BUFSZ) + b_lane;

                #pragma unroll
                for (int kp = 0; kp < 4; ++kp) {
                    // A fragments for both k16 halves
                    uint32_t ah[2][2][4];                // [ks2][mtile][4]
                    #pragma unroll
                    for (int ks2 = 0; ks2 < 2; ++ks2) {
                        const uint32_t koff = (uint32_t)((kp * 2 + ks2) * 32);
                        ldsm4(ah[ks2][0], abA + aoffm0 + koff);
                        ldsm4(ah[ks2][1], abA + aoffm1 + koff);
                    }
                    // B fragments from SMEM (conflict-free LDS.128)
                    uint32_t bfr[4][4];
                    #pragma unroll
                    for (int nt = 0; nt < 4; ++nt)
                        lds128(bfr[nt], bbB + (uint32_t)(nt * 2048 + kp * 512));
                    #pragma unroll
                    for (int ks2 = 0; ks2 < 2; ++ks2)
                        #pragma unroll
                        for (int nt = 0; nt < 4; ++nt) {
                            const uint32_t b0 = ks2 ? bfr[nt][2] : bfr[nt][0];
                            const uint32_t b1 = ks2 ? bfr[nt][3] : bfr[nt][1];
                            mma16816(acc[0][nt], ah[ks2][0], b0, b1);
                            mma16816(acc[1][nt], ah[ks2][1], b0, b1);
                        }
                }
                __syncthreads();          // guard A/B buffer overwrite next iter
            }

            // ---- epilogue: + Wx[value] + b_ih, fast tanh, store h (fp16) ----
            #pragma unroll
            for (int mt = 0; mt < 2; ++mt) {
                const int r1 = wm + mt * 16 + (lane >> 2);
                const int r2 = r1 + 8;
                const int v1 = iv[r1], v2 = iv[r2];
                const int o1 = io[r1], o2 = io[r2];
                #pragma unroll
                for (int nt = 0; nt < 4; ++nt) {
                    const int gcol = hp * NQ + wgn * 32 + nt * 8 + (lane & 3) * 2;
                    const float2 bv = *(const float2*)(bih + gcol);
                    if (v1 >= 0) {
                        const float2 wx = __ldg((const float2*)(W_ih + (size_t)v1 * HID_ + gcol));
                        const __half2 o2h = __floats2half2_rn(
                            ftanh(acc[mt][nt][0] + wx.x + bv.x),
                            ftanh(acc[mt][nt][1] + wx.y + bv.y));
                        *(__half2*)(g_H + (size_t)o1 * HID_ + gcol) = o2h;
                    }
                    if (v2 >= 0) {
                        const float2 wx = __ldg((const float2*)(W_ih + (size_t)v2 * HID_ + gcol));
                        const __half2 o2h = __floats2half2_rn(
                            ftanh(acc[mt][nt][2] + wx.x + bv.x),
                            ftanh(acc[mt][nt][3] + wx.y + bv.y));
                        *(__half2*)(g_H + (size_t)o2 * HID_ + gcol) = o2h;
                    }
                }
            }
            __syncthreads();   // meta/A reuse protection for next item
        }
        grid_barrier((unsigned)lvl, nct);
    }
    #undef GATHER
    #undef STAGE_B
}

// ============================================================================
// Barrier state reset (graph-replay determinism)
// ============================================================================
extern "C" __global__ void k_reset()
{
    if (threadIdx.x == 0) { g_epoch = 0u; g_barcnt = 0u; }
}

// ============================================================================
// Output kernel: logits = h_root @ W_o + b_o, then log_softmax
// ============================================================================
extern "C" __global__ void __launch_bounds__(64)
rnn_out(const float* __restrict__ W_o,
        const float* __restrict__ b_o,
        float* __restrict__ out)
{
    __shared__ float hs[HID_];
    __shared__ float lg[OUT_];
    __shared__ float lse;
    const int b   = blockIdx.x;
    const int tid = threadIdx.x;

    const __half* hrow = g_H + ((size_t)b * (N_ + 1) + (N_ - 1)) * HID_;
    {
        const uint4 v = *(const uint4*)(hrow + tid * 8);
        const __half2* h2 = (const __half2*)&v;
        #pragma unroll
        for (int j = 0; j < 4; ++j) {
            const float2 f = __half22float2(h2[j]);
            hs[tid * 8 + j * 2 + 0] = f.x;
            hs[tid * 8 + j * 2 + 1] = f.y;
        }
    }
    __syncthreads();

    if (tid < OUT_) {
        float acc = b_o[tid];
        #pragma unroll 8
        for (int k = 0; k < HID_; ++k)
            acc = fmaf(hs[k], __ldg(W_o + (size_t)k * OUT_ + tid), acc);
        lg[tid] = acc;
    }
    __syncthreads();

    if (tid == 0) {
        float m = -1e30f;
        for (int j = 0; j < OUT_; ++j) m = fmaxf(m, lg[j]);
        float ssum = 0.f;
        for (int j = 0; j < OUT_; ++j) ssum += expf(lg[j] - m);
        lse = m + logf(ssum);
    }
    __syncthreads();

    if (tid < OUT_) out[(size_t)b * OUT_ + tid] = lg[tid] - lse;
}

// ============================================================================
// Launcher: 6 graph nodes, capturable, allocation-free.
// ============================================================================
extern "C" void kernel_launch(void* const* d_in, const int* in_sizes, int n_in,
                              void* d_out, int out_size)
{
    (void)in_sizes; (void)n_in; (void)out_size;
    const int*   left  = (const int*)d_in[0];
    const int*   right = (const int*)d_in[1];
    const int*   vals  = (const int*)d_in[2];
    const float* W_ih  = (const float*)d_in[3];
    const float* b_ih  = (const float*)d_in[4];
    const float* W_o   = (const float*)d_in[5];
    const float* b_o   = (const float*)d_in[6];
    float*       out   = (float*)d_out;

    cudaFuncSetAttribute(rnn_main,
                         cudaFuncAttributeMaxDynamicSharedMemorySize, SMEM_MAIN);

    k_levels<<<B_, 128>>>(left, right);
    k_prefix<<<1, 256>>>();
    k_scatter<<<B_, 128>>>(W_ih);
    rnn_main<<<GRID_MAIN, THR_MAIN, SMEM_MAIN>>>(left, right, vals, W_ih, b_ih);
    k_reset<<<1, 1>>>();
    rnn_out<<<B_, 64>>>(W_o, b_o, out);
}

// round 17
// speedup vs baseline: 1.1132x; 1.1132x over previous
#include <cuda_runtime.h>
#include <cuda_fp16.h>
#include <math.h>
#include <stdint.h>

// Problem constants
#define B_    256
#define N_    512
#define HID_  512
#define IN_   57
#define OUT_  57

#define MAXL      513
#define GRID_MAIN 296            // 2 CTAs/SM x 148 SMs, co-resident
#define THR_MAIN  256
#define MT        64             // nodes (rows) per item
#define NQ        128            // cols per item (quarter of N)

// ---------------- device globals ----------------
__device__ __half         g_H[(size_t)B_ * (N_ + 1) * HID_];   // fp16 h; row N_ (b=0) = zero sentinel
__device__ __half         g_Wb[HID_ * HID_];      // fragment-packed Wh^T (fp16)
__device__ unsigned short g_lvl[B_ * N_];
__device__ int            g_cntb[MAXL * B_];
__device__ int            g_base[MAXL * B_];
__device__ int            g_off[MAXL + 1];
__device__ int            g_nodes[B_ * N_];
__device__ int            g_nlv;
__device__ unsigned       g_barcnt;
__device__ unsigned       g_epoch;

// ---------------- SMEM layout ----------------
// A plane (fp16): [3 buf][64 rows][136 fp16] row stride 272 B
#define A_STRIDE 272
#define A_BUFSZ  (MT * A_STRIDE)         // 17408
#define SM_A     0                       // 3 * 17408 = 52224
#define SM_BIH   52224                   // 512 f32 = 2048
#define SM_META  54272                   // il/ir/iv/io [64] each = 1024
#define SMEM_MAIN 55296                  // x2 CTAs = 110592 < 227KB/SM

// ---------------- PTX helpers (baseline ISA only) ----------------
__device__ __forceinline__ void mma16816(float* d, const uint32_t* a,
                                         uint32_t b0, uint32_t b1) {
    asm volatile(
        "mma.sync.aligned.m16n8k16.row.col.f32.f16.f16.f32 "
        "{%0,%1,%2,%3}, {%4,%5,%6,%7}, {%8,%9}, {%0,%1,%2,%3};\n"
        : "+f"(d[0]), "+f"(d[1]), "+f"(d[2]), "+f"(d[3])
        : "r"(a[0]), "r"(a[1]), "r"(a[2]), "r"(a[3]), "r"(b0), "r"(b1));
}
__device__ __forceinline__ void ldsm4(uint32_t* r, uint32_t a) {
    asm volatile("ldmatrix.sync.aligned.m8n8.x4.shared.b16 {%0,%1,%2,%3}, [%4];\n"
        : "=r"(r[0]), "=r"(r[1]), "=r"(r[2]), "=r"(r[3]) : "r"(a));
}
__device__ __forceinline__ uint32_t smem_u32(const void* p) {
    return (uint32_t)__cvta_generic_to_shared(p);
}

// FFMA-only tanh: tanh(x) = 1 - 2/(e^{2x}+1); exp2 via round-trick + deg-7
// Taylor; reciprocal via bit-trick seed + 3 Newton. No MUFU, no CVT.
__device__ __forceinline__ float ftanh(float x) {
    float t = fminf(fmaxf(x, -15.0f), 15.0f);
    float z = t * 2.8853900817779268f;           // 2*log2(e)*x
    float zk = z + 12582912.0f;                   // round-to-nearest-even
    float k  = zk - 12582912.0f;
    float f  = z - k;                             // f in [-0.5, 0.5]
    float p = 1.5252733814e-5f;
    p = fmaf(p, f, 1.5403530394e-4f);
    p = fmaf(p, f, 1.3333558146e-3f);
    p = fmaf(p, f, 9.6181291076e-3f);
    p = fmaf(p, f, 5.5504108664e-2f);
    p = fmaf(p, f, 2.4022650696e-1f);
    p = fmaf(p, f, 6.9314718056e-1f);
    p = fmaf(p, f, 1.0f);
    const int ib = __float_as_int(zk);
    const float sc = __int_as_float((ib + (127 - 0x4B400000)) << 23);   // 2^k
    const float E = p * sc;                       // e^{2x}
    const float d = E + 1.0f;
    float r = __int_as_float(0x7EF311C3 - __float_as_int(d));
    r = r * fmaf(-d, r, 2.0f);
    r = r * fmaf(-d, r, 2.0f);
    r = r * fmaf(-d, r, 2.0f);
    return fmaf(-2.0f, r, 1.0f);
}

// ============================================================================
// Prep kernels
// ============================================================================
extern "C" __global__ void __launch_bounds__(128)
k_levels(const int* __restrict__ L, const int* __restrict__ R)
{
    __shared__ int sli[N_], sri[N_], shist[MAXL];
    __shared__ unsigned short slv[N_];
    const int b = blockIdx.x, tid = threadIdx.x;
    for (int i = tid; i < N_; i += 128) { sli[i] = L[b * N_ + i]; sri[i] = R[b * N_ + i]; }
    for (int i = tid; i < MAXL; i += 128) shist[i] = 0;
    __syncthreads();
    if (tid == 0) {
        for (int i = 0; i < N_; ++i) {
            const int l = sli[i], r = sri[i];
            const int a = (l < 0) ? 0 : (int)slv[l];
            const int c = (r < 0) ? 0 : (int)slv[r];
            const int lv = 1 + (a > c ? a : c);
            slv[i] = (unsigned short)lv;
            shist[lv]++;
        }
    }
    __syncthreads();
    for (int i = tid; i < N_; i += 128) g_lvl[b * N_ + i] = slv[i];
    for (int l = tid; l < MAXL; l += 128) g_cntb[l * B_ + b] = shist[l];
}

extern "C" __global__ void __launch_bounds__(256)
k_prefix()
{
    __shared__ int tot[MAXL];
    __shared__ int offs[MAXL + 1];
    const int tid = threadIdx.x;
    for (int l = tid; l < MAXL; l += 256) {
        int run = 0; const int base = l * B_;
        #pragma unroll 4
        for (int b = 0; b < B_; ++b) { const int c = g_cntb[base + b]; g_base[base + b] = run; run += c; }
        tot[l] = run;
    }
    __syncthreads();
    if (tid == 0) {
        int run = 0, mx = 1;
        for (int l = 0; l < MAXL; ++l) { offs[l] = run; run += tot[l]; if (tot[l] > 0) mx = l; }
        offs[MAXL] = run;
        g_nlv = mx;
    }
    __syncthreads();
    for (int idx = tid; idx < MAXL * B_; idx += 256) g_base[idx] += offs[idx >> 8];
    for (int l = tid; l <= MAXL; l += 256) g_off[l] = offs[l];
}

// counting-sort scatter + Wh transpose/pack (merged)
extern "C" __global__ void __launch_bounds__(128)
k_scatter(const float* __restrict__ W_ih)
{
    __shared__ unsigned short slv[N_];
    __shared__ int cur[MAXL];
    __shared__ int pos[N_];
    const int b = blockIdx.x, tid = threadIdx.x;
    for (int i = tid; i < N_; i += 128) slv[i] = g_lvl[b * N_ + i];
    for (int l = tid; l < MAXL; l += 128) cur[l] = g_base[l * B_ + b];
    __syncthreads();
    if (tid == 0)
        for (int i = 0; i < N_; ++i) { const int l = slv[i]; pos[i] = cur[l]++; }
    __syncthreads();
    for (int i = tid; i < N_; i += 128) g_nodes[pos[i]] = (b << 9) | i;

    // ---- Wh transpose + fp16 pack, fragment layout for mma.B ----
    // u32 index = ((n_tile*16 + kpair)*32 + lane)*4 + ko*2 + word
    for (int t = tid; t < 2 * HID_; t += 128) {
        const int n = 2 * b + (t >> 9);          // 2 n-rows per block
        const int k = t & (HID_ - 1);
        const float w = W_ih[(size_t)(IN_ + k) * HID_ + n];
        const __half h = __float2half_rn(w);
        const int n_tile = n >> 3, kpair = k >> 5, ko = (k >> 4) & 1;
        const int lane = ((n & 7) << 2) | ((k >> 1) & 3);
        const int word = (k >> 3) & 1, elem = k & 1;
        const size_t u32i = ((size_t)(n_tile * 16 + kpair) * 32 + lane) * 4 + ko * 2 + word;
        g_Wb[u32i * 2 + elem] = h;
    }
}

// ============================================================================
// Grid-wide software barrier (pure acquire-spin; CTAs co-resident)
// ============================================================================
__device__ __forceinline__ void grid_barrier(unsigned tgt, unsigned nct)
{
    __syncthreads();
    if (threadIdx.x == 0) {
        __threadfence();
        const unsigned a = atomicAdd(&g_barcnt, 1u);
        if (a == nct - 1u) {
            g_barcnt = 0u;
            __threadfence();
            atomicExch(&g_epoch, tgt);
        } else {
            unsigned e;
            do {
                asm volatile("ld.acquire.gpu.u32 %0, [%1];"
                             : "=r"(e) : "l"((unsigned*)&g_epoch) : "memory");
            } while (e < tgt);
        }
    }
    __syncthreads();
}

// ============================================================================
// Main persistent kernel: level-parallel single-pass fp16 HMMA GEMM + tanh.
// Item: 64 nodes x 128 cols. Warp tile: 32 rows x 32 cols (2x4 warp grid).
// A = h_l + h_r (fp16 add), TRIPLE-buffered SMEM (1 sync per chunk).
// B = direct LDG, register-pipelined one kp ahead (gkp = 0..15).
// ============================================================================
extern "C" __global__ void __launch_bounds__(THR_MAIN, 2)
rnn_main(const int* __restrict__ L, const int* __restrict__ R,
         const int* __restrict__ V, const float* __restrict__ W_ih,
         const float* __restrict__ b_ih)
{
    extern __shared__ char sm[];
    const uint32_t smem_base = smem_u32(sm);
    float* bih = (float*)(sm + SM_BIH);
    int*   il  = (int*)(sm + SM_META);
    int*   ir  = il + MT;
    int*   iv  = ir + MT;
    int*   io  = iv + MT;

    const int tid  = threadIdx.x;
    const int wid  = tid >> 5, lane = tid & 31;

    for (int i = tid; i < HID_; i += THR_MAIN) bih[i] = b_ih[i];

    // warp tiling: 2 row groups x 4 col groups (32 cols each)
    const int wm  = (wid & 1) * 32;          // warp row base
    const int wgn = wid >> 1;                // col group (0..3)
    const uint32_t a_lane = (uint32_t)((lane & 15) * A_STRIDE + (lane >> 4) * 16);
    const uint32_t aoffm0 = (uint32_t)(wm * A_STRIDE);
    const uint32_t aoffm1 = (uint32_t)((wm + 16) * A_STRIDE);

    const int nlv = g_nlv;
    const unsigned nct = gridDim.x;

    // gather mapping: row = tid>>2, k-quarter = tid&3 (32 halves = 4 uint4)
    const int grow = tid >> 2, gks = tid & 3;

    #define GATHER(c, bf)                                                        \
    {                                                                            \
        const uint4* pl = (const uint4*)(g_H + (size_t)il[grow] * HID_)          \
                          + ((c) * 16 + gks * 4);                                \
        const uint4* pr = (const uint4*)(g_H + (size_t)ir[grow] * HID_)          \
                          + ((c) * 16 + gks * 4);                                \
        uint4 la[4], ra[4];                                                      \
        _Pragma("unroll")                                                        \
        for (int q = 0; q < 4; ++q) { la[q] = __ldcg(pl + q); ra[q] = __ldcg(pr + q); } \
        char* dh = sm + SM_A + (bf) * A_BUFSZ + grow * A_STRIDE + gks * 64;      \
        _Pragma("unroll")                                                        \
        for (int q = 0; q < 4; ++q) {                                            \
            const __half2* a2 = (const __half2*)&la[q];                          \
            const __half2* b2 = (const __half2*)&ra[q];                          \
            __half2 s0 = __hadd2(a2[0], b2[0]);                                  \
            __half2 s1 = __hadd2(a2[1], b2[1]);                                  \
            __half2 s2 = __hadd2(a2[2], b2[2]);                                  \
            __half2 s3 = __hadd2(a2[3], b2[3]);                                  \
            ((uint4*)dh)[q] = make_uint4(*(uint32_t*)&s0, *(uint32_t*)&s1,       \
                                         *(uint32_t*)&s2, *(uint32_t*)&s3);      \
        }                                                                        \
    }

    for (int lvl = 1; lvl <= nlv; ++lvl) {
        const int s = g_off[lvl], e = g_off[lvl + 1];
        const int items = ((e - s + MT - 1) >> 6) * 4;
        for (int w = blockIdx.x; w < items; w += (int)nct) {
            const int rt = w >> 2, hp = w & 3;            // row tile / col quarter
            const int t0 = s + rt * MT;
            const int ntb = hp * 16 + wgn * 4;            // global n-tile base

            // ---- node metadata ----
            if (tid < MT) {
                const int gi = t0 + tid;
                if (gi < e) {
                    const int nd = g_nodes[gi];
                    const int b = nd >> 9, i = nd & (N_ - 1);
                    int l = L[b * N_ + i]; if (l < 0) l = N_;
                    int r = R[b * N_ + i]; if (r < 0) r = N_;
                    il[tid] = b * (N_ + 1) + l;
                    ir[tid] = b * (N_ + 1) + r;
                    iv[tid] = V[b * N_ + i];
                    io[tid] = b * (N_ + 1) + i;
                } else {
                    il[tid] = N_;     // zero sentinel row (b=0)
                    ir[tid] = N_;
                    iv[tid] = -1;
                }
            }
            __syncthreads();

            float acc[2][4][4];
            #pragma unroll
            for (int mt = 0; mt < 2; ++mt)
                #pragma unroll
                for (int nt = 0; nt < 4; ++nt)
                    #pragma unroll
                    for (int q = 0; q < 4; ++q) acc[mt][nt][q] = 0.0f;

            // B fragment pointer for this warp/item (gkp-indexed)
            const uint4* bbase = (const uint4*)g_Wb + (size_t)ntb * 16 * 32 + lane;

            // prologue: gather chunk 0, preload B gkp 0
            GATHER(0, 0)
            uint4 bcur[4], bnxt[4];
            #pragma unroll
            for (int nt = 0; nt < 4; ++nt)
                bcur[nt] = __ldg(bbase + (size_t)nt * 512);
            __syncthreads();      // A chunk 0 visible

            #pragma unroll
            for (int c = 0; c < 4; ++c) {
                if (c < 3) GATHER(c + 1, (c + 1) % 3)

                const uint32_t abA = smem_base + SM_A
                    + (uint32_t)((c % 3) * A_BUFSZ) + a_lane;

                #pragma unroll
                for (int kp = 0; kp < 4; ++kp) {
                    const int gkp = c * 4 + kp;
                    // prefetch B for gkp+1 (lands during this kp's mma work)
                    if (gkp < 15) {
                        #pragma unroll
                        for (int nt = 0; nt < 4; ++nt)
                            bnxt[nt] = __ldg(bbase + (size_t)nt * 512 + (gkp + 1) * 32);
                    }
                    // A fragments just-in-time per k16 half
                    #pragma unroll
                    for (int ks2 = 0; ks2 < 2; ++ks2) {
                        uint32_t a0[4], a1[4];
                        const uint32_t koff = (uint32_t)((kp * 2 + ks2) * 32);
                        ldsm4(a0, abA + aoffm0 + koff);
                        ldsm4(a1, abA + aoffm1 + koff);
                        #pragma unroll
                        for (int nt = 0; nt < 4; ++nt) {
                            const uint32_t b0 = ks2 ? bcur[nt].z : bcur[nt].x;
                            const uint32_t b1 = ks2 ? bcur[nt].w : bcur[nt].y;
                            mma16816(acc[0][nt], a0, b0, b1);
                            mma16816(acc[1][nt], a1, b0, b1);
                        }
                    }
                    #pragma unroll
                    for (int nt = 0; nt < 4; ++nt) bcur[nt] = bnxt[nt];
                }
                if (c < 3) __syncthreads();   // A chunk c+1 visible; buf reuse safe
            }

            // ---- epilogue: + Wx[value] + b_ih, fast tanh, store h (fp16) ----
            #pragma unroll
            for (int mt = 0; mt < 2; ++mt) {
                const int r1 = wm + mt * 16 + (lane >> 2);
                const int r2 = r1 + 8;
                const int v1 = iv[r1], v2 = iv[r2];
                const int o1 = io[r1], o2 = io[r2];
                #pragma unroll
                for (int nt = 0; nt < 4; ++nt) {
                    const int gcol = hp * NQ + wgn * 32 + nt * 8 + (lane & 3) * 2;
                    const float2 bv = *(const float2*)(bih + gcol);
                    if (v1 >= 0) {
                        const float2 wx = __ldg((const float2*)(W_ih + (size_t)v1 * HID_ + gcol));
                        const __half2 o2h = __floats2half2_rn(
                            ftanh(acc[mt][nt][0] + wx.x + bv.x),
                            ftanh(acc[mt][nt][1] + wx.y + bv.y));
                        *(__half2*)(g_H + (size_t)o1 * HID_ + gcol) = o2h;
                    }
                    if (v2 >= 0) {
                        const float2 wx = __ldg((const float2*)(W_ih + (size_t)v2 * HID_ + gcol));
                        const __half2 o2h = __floats2half2_rn(
                            ftanh(acc[mt][nt][2] + wx.x + bv.x),
                            ftanh(acc[mt][nt][3] + wx.y + bv.y));
                        *(__half2*)(g_H + (size_t)o2 * HID_ + gcol) = o2h;
                    }
                }
            }
            __syncthreads();   // meta/A reuse protection for next item
        }
        grid_barrier((unsigned)lvl, nct);
    }
    #undef GATHER
}

// ============================================================================
// Barrier state reset (graph-replay determinism)
// ============================================================================
extern "C" __global__ void k_reset()
{
    if (threadIdx.x == 0) { g_epoch = 0u; g_barcnt = 0u; }
}

// ============================================================================
// Output kernel: logits = h_root @ W_o + b_o, then log_softmax
// ============================================================================
extern "C" __global__ void __launch_bounds__(64)
rnn_out(const float* __restrict__ W_o,
        const float* __restrict__ b_o,
        float* __restrict__ out)
{
    __shared__ float hs[HID_];
    __shared__ float lg[OUT_];
    __shared__ float lse;
    const int b   = blockIdx.x;
    const int tid = threadIdx.x;

    const __half* hrow = g_H + ((size_t)b * (N_ + 1) + (N_ - 1)) * HID_;
    {
        const uint4 v = *(const uint4*)(hrow + tid * 8);
        const __half2* h2 = (const __half2*)&v;
        #pragma unroll
        for (int j = 0; j < 4; ++j) {
            const float2 f = __half22float2(h2[j]);
            hs[tid * 8 + j * 2 + 0] = f.x;
            hs[tid * 8 + j * 2 + 1] = f.y;
        }
    }
    __syncthreads();

    if (tid < OUT_) {
        float acc = b_o[tid];
        #pragma unroll 8
        for (int k = 0; k < HID_; ++k)
            acc = fmaf(hs[k], __ldg(W_o + (size_t)k * OUT_ + tid), acc);
        lg[tid] = acc;
    }
    __syncthreads();

    if (tid == 0) {
        float m = -1e30f;
        for (int j = 0; j < OUT_; ++j) m = fmaxf(m, lg[j]);
        float ssum = 0.f;
        for (int j = 0; j < OUT_; ++j) ssum += expf(lg[j] - m);
        lse = m + logf(ssum);
    }
    __syncthreads();

    if (tid < OUT_) out[(size_t)b * OUT_ + tid] = lg[tid] - lse;
}

// ============================================================================
// Launcher: 6 graph nodes, capturable, allocation-free.
// ============================================================================
extern "C" void kernel_launch(void* const* d_in, const int* in_sizes, int n_in,
                              void* d_out, int out_size)
{
    (void)in_sizes; (void)n_in; (void)out_size;
    const int*   left  = (const int*)d_in[0];
    const int*   right = (const int*)d_in[1];
    const int*   vals  = (const int*)d_in[2];
    const float* W_ih  = (const float*)d_in[3];
    const float* b_ih  = (const float*)d_in[4];
    const float* W_o   = (const float*)d_in[5];
    const float* b_o   = (const float*)d_in[6];
    float*       out   = (float*)d_out;

    cudaFuncSetAttribute(rnn_main,
                         cudaFuncAttributeMaxDynamicSharedMemorySize, SMEM_MAIN);

    k_levels<<<B_, 128>>>(left, right);
    k_prefix<<<1, 256>>>();
    k_scatter<<<B_, 128>>>(W_ih);
    rnn_main<<<GRID_MAIN, THR_MAIN, SMEM_MAIN>>>(left, right, vals, W_ih, b_ih);
    k_reset<<<1, 1>>>();
    rnn_out<<<B_, 64>>>(W_o, b_o, out);
}